// round 11
// baseline (speedup 1.0000x reference)
#include <cuda_runtime.h>

// Caps_Layer: B=128, N=512, D=300, NC=10, DC=64, ROUTINGS=5  (fused, 1 CTA/batch)
// u = x@W never materialized. Per iteration:
//   P2: o_raw[m] = sum_d y[i,d] W[d,m] ; squash -> o
//   P3: v[i,d] = sum_k o[i,k] Wt[i*64+k,d]              (pre-transposed W)
//   XPASS (warp-specialized pipeline over 8 j-tiles of 64):
//     wg0 (warps 0-9):  prefetch x tiles (2-buffer ring); B(k): b=x*v, each v
//                       broadcast feeds 2 j columns (lane, lane+32)
//     wg1 (warps 10-19): softmax(k) (bp -> cb, 4 clamped rounds) ; C(k): y += c*x
//     bars: id1 B(k)->wg1 ; id2 C(k) done -> wg0 ; id3 wg0-local cp visibility ;
//           id4 wg1-local cb visibility ; id5 softmax(k-1) done -> wg0 may write bp.

#define NN 512
#define DD 300
#define NC 10
#define DC 64
#define MM 640
#define BB 128
#define NT 640
#define TJ 64
#define NTILE 8
#define AR_BUF (TJ * DD)          // 19200 floats per buffer

#define OFF_AR  0                 // 2 buffers = 38400 (yp[6000] overlays buf0 at flush)
#define OFF_V   38400             // 3000
#define OFF_Y   41400             // 3000
#define OFF_BP  44400             // 7040 = 10 warps * 704 (also P2 scratch 2560, it0 600)
#define OFF_C   51440             // 768  (c[j*12 + i], 64 j)
#define OFF_O   52208             // 640
#define OFF_NRM 52848             // 16
#define SMEM_FLOATS 52864
#define SMEM_BYTES (SMEM_FLOATS * 4)   // 211456 B

typedef unsigned long long u64;
struct u64x2_t { u64 x, y; };

__device__ float Wt_g[MM * DD];   // W transposed: Wt[m*300 + d]

__device__ __forceinline__ void fma2(u64& acc, u64 a, u64 b) {
    asm("fma.rn.f32x2 %0, %1, %2, %0;" : "+l"(acc) : "l"(a), "l"(b));
}
__device__ __forceinline__ u64 splat2(float f) {
    u64 r; asm("mov.b64 %0, {%1,%1};" : "=l"(r) : "f"(f)); return r;
}
__device__ __forceinline__ float fold2(u64 v) {
    float lo, hi; asm("mov.b64 {%0,%1}, %2;" : "=f"(lo), "=f"(hi) : "l"(v)); return lo + hi;
}
__device__ __forceinline__ void cp16(void* smem_dst, const void* gsrc) {
    unsigned sa = (unsigned)__cvta_generic_to_shared(smem_dst);
    asm volatile("cp.async.cg.shared.global [%0], [%1], 16;" :: "r"(sa), "l"(gsrc));
}
__device__ __forceinline__ void cp_commit() { asm volatile("cp.async.commit_group;"); }
template <int N> __device__ __forceinline__ void cp_wait() {
    asm volatile("cp.async.wait_group %0;" :: "n"(N));
}
__device__ __forceinline__ void bar_arrive(int id, int cnt) {
    asm volatile("bar.arrive %0, %1;" :: "r"(id), "r"(cnt) : "memory");
}
__device__ __forceinline__ void bar_sync(int id, int cnt) {
    asm volatile("bar.sync %0, %1;" :: "r"(id), "r"(cnt) : "memory");
}

// ---------------- prologue: W[300][640] -> Wt[640][300] ----------------
__global__ void transpose_W(const float* __restrict__ W)
{
    __shared__ float tl[32][33];
    const int tx = threadIdx.x, ty = threadIdx.y;     // 32 x 8
    const int m0 = blockIdx.x * 32, d0 = blockIdx.y * 32;
    #pragma unroll
    for (int k = 0; k < 4; ++k) {
        const int d = d0 + ty + k * 8;
        if (d < DD) tl[ty + k * 8][tx] = W[(size_t)d * MM + m0 + tx];
    }
    __syncthreads();
    #pragma unroll
    for (int k = 0; k < 4; ++k) {
        const int m = m0 + ty + k * 8;
        const int d = d0 + tx;
        if (d < DD) Wt_g[(size_t)m * DD + d] = tl[tx][ty + k * 8];
    }
}

__global__ __launch_bounds__(NT, 1)
void caps_kernel(const float* __restrict__ x,
                 const float* __restrict__ W,
                 float* __restrict__ out)
{
    extern __shared__ float sm[];
    const int b    = blockIdx.x;
    const int t    = threadIdx.x;
    const int w    = t >> 5;
    const int lane = t & 31;
    const float* __restrict__ xb = x + (size_t)b * NN * DD;

    float* v_s  = sm + OFF_V;
    float* y_s  = sm + OFF_Y;
    float* bp   = sm + OFF_BP;
    float* cb   = sm + OFF_C;
    float* o_s  = sm + OFF_O;
    float* nrm  = sm + OFF_NRM;
    float* yp   = sm + OFF_AR;        // overlay on ring buf0, valid only at flush

    // ---- iteration 0: y[i,d] = 0.1 * colsum_d(x) ----
    if (t < 600) {
        const int g = t / 300, d = t - g * 300;
        const float* __restrict__ xp = xb + (size_t)(g * 256) * DD + d;
        float a0 = 0.f, a1 = 0.f, a2 = 0.f, a3 = 0.f;
        for (int j = 0; j < 256; j += 4) {
            a0 += xp[(j + 0) * DD]; a1 += xp[(j + 1) * DD];
            a2 += xp[(j + 2) * DD]; a3 += xp[(j + 3) * DD];
        }
        bp[g * 300 + d] = (a0 + a1) + (a2 + a3);
    }
    __syncthreads();
    for (int idx = t; idx < NC * DD; idx += NT) {
        const int d = idx % DD;
        y_s[idx] = 0.1f * (bp[d] + bp[300 + d]);
    }
    __syncthreads();

    for (int r = 0; r < 5; ++r) {
        // ---------------- P2: o_raw[m] = sum_d y[i,d] W[d,m] ----------------
        {
            const int ds  = t / 160;            // d-slice 0..3
            const int m4  = (t - ds * 160) * 4; // 4 consecutive m
            const int ci  = m4 >> 6;
            const int d0  = ds * 75;
            const float* __restrict__ ypt = y_s + ci * DD;
            u64 a01 = 0ull, a23 = 0ull;
            #pragma unroll 5
            for (int d = d0; d < d0 + 75; ++d) {
                const u64x2_t w4 = *(const u64x2_t*)(W + (size_t)d * MM + m4);
                const u64 ys = splat2(ypt[d]);
                fma2(a01, w4.x, ys); fma2(a23, w4.y, ys);
            }
            *(u64*)(bp + ds * MM + m4)     = a01;
            *(u64*)(bp + ds * MM + m4 + 2) = a23;
        }
        __syncthreads();
        o_s[t] = bp[t] + bp[MM + t] + bp[2 * MM + t] + bp[3 * MM + t];
        __syncthreads();
        if (t < 320) {   // squash norms
            const int i = t >> 5;
            const float v0 = o_s[i * DC + lane];
            const float v1 = o_s[i * DC + 32 + lane];
            float s = v0 * v0 + v1 * v1;
            #pragma unroll
            for (int k = 16; k > 0; k >>= 1) s += __shfl_xor_sync(0xffffffffu, s, k);
            if (lane == 0) nrm[i] = rsqrtf(s + 1e-7f);
        }
        __syncthreads();
        const float ov = o_s[t] * nrm[t >> 6];
        o_s[t] = ov;
        if (r == 4) { out[(size_t)b * MM + t] = ov; break; }
        __syncthreads();

        // ---------------- P3: v[i,d] = sum_k o[i,k] Wt[i*64+k, d] ----------------
        for (int idx = t; idx < NC * 150; idx += NT) {
            const int i  = idx / 150;
            const int d0 = (idx - i * 150) * 2;
            const float* __restrict__ ob = o_s + i * DC;
            const float* __restrict__ wt = Wt_g + (size_t)i * DC * DD + d0;
            u64 acc = 0ull;
            #pragma unroll 8
            for (int k = 0; k < DC; ++k)
                fma2(acc, *(const u64*)(wt + (size_t)k * DD), splat2(ob[k]));
            *(u64*)(v_s + i * DD + d0) = acc;
        }
        __syncthreads();

        // ---------------- XPASS: warp-specialized pipeline, 8 tiles of 64 j ----------------
        if (t < 320) {
            // ===== wg0: prefetch + B =====
            for (int idx = t; idx < AR_BUF / 4; idx += 320)
                cp16(sm + OFF_AR + idx * 4, xb + idx * 4);
            cp_commit();

            const int dB  = (w < 9) ? w * 32 : 288;
            const int n16 = (w < 9) ? 8 : 3;

            for (int k = 0; k < NTILE; ++k) {
                if (k >= 1) bar_sync(2, 640);        // C(k-1) done: buf (k+1)&1 free
                if (k + 1 < NTILE) {
                    const float* gs = xb + (size_t)(k + 1) * AR_BUF;
                    float* dst = sm + OFF_AR + ((k + 1) & 1) * AR_BUF;
                    for (int idx = t; idx < AR_BUF / 4; idx += 320)
                        cp16(dst + idx * 4, gs + idx * 4);
                    cp_commit();
                    cp_wait<1>();                    // tile k landed
                } else {
                    cp_wait<0>();
                }
                bar_sync(3, 320);                    // cp data visible across wg0
                if (k >= 1) bar_sync(5, 640);        // softmax(k-1) done: bp free
                const float* xs = sm + OFF_AR + (k & 1) * AR_BUF;

                // ---- B: b[i, j=lane] and b[i, j=lane+32], shared v broadcasts ----
                {
                    u64 accA[NC], accB[NC];
                    #pragma unroll
                    for (int i = 0; i < NC; ++i) { accA[i] = 0ull; accB[i] = 0ull; }
                    const float* xrowA = xs + lane * DD + dB;
                    const float* xrowB = xs + (lane + 32) * DD + dB;
                    for (int s = 0; s < n16; ++s) {
                        const u64x2_t xvA = *(const u64x2_t*)(xrowA + s * 4);
                        const u64x2_t xvB = *(const u64x2_t*)(xrowB + s * 4);
                        #pragma unroll
                        for (int i = 0; i < NC; ++i) {
                            const u64x2_t vv = *(const u64x2_t*)(v_s + i * DD + dB + s * 4);
                            fma2(accA[i], xvA.x, vv.x);
                            fma2(accA[i], xvA.y, vv.y);
                            fma2(accB[i], xvB.x, vv.x);
                            fma2(accB[i], xvB.y, vv.y);
                        }
                    }
                    #pragma unroll
                    for (int i = 0; i < NC; ++i) {
                        bp[w * 704 + lane * 11 + i]        = fold2(accA[i]);
                        bp[w * 704 + (lane + 32) * 11 + i] = fold2(accB[i]);
                    }
                }
                bar_arrive(1, 640);                  // B(k) ready for wg1
            }
            bar_sync(2, 640);                        // consume C(last)
        } else {
            // ===== wg1: softmax + C =====
            const int t2  = t - 320;                 // 0..319
            const int jg  = t2 / 150;                // valid for t2<300
            const int d0c = (t2 - jg * 150) * 2;
            const int j0  = jg * 32;
            u64 yacc[NC];
            #pragma unroll
            for (int i = 0; i < NC; ++i) yacc[i] = 0ull;

            for (int k = 0; k < NTILE; ++k) {
                bar_sync(1, 640);                    // wait B(k)
                const float* xs = sm + OFF_AR + (k & 1) * AR_BUF;

                // ---- softmax over i per j: 4 rounds of 20 groups (clamped) ----
                #pragma unroll
                for (int rd = 0; rd < 4; ++rd) {
                    const int jr = rd * 20 + (t2 >> 4);
                    const int j  = (jr < 64) ? jr : 63;   // clamp: redundant compute, no divergence
                    const int ii = t2 & 15;
                    float s;
                    if (ii < NC) {
                        s = 0.f;
                        #pragma unroll
                        for (int ww = 0; ww < 10; ++ww)
                            s += bp[ww * 704 + j * 11 + ii];
                    } else s = -1e30f;
                    float m = s;
                    #pragma unroll
                    for (int kk = 8; kk > 0; kk >>= 1)
                        m = fmaxf(m, __shfl_xor_sync(0xffffffffu, m, kk, 16));
                    const float e = __expf(s - m);
                    float su = e;
                    #pragma unroll
                    for (int kk = 8; kk > 0; kk >>= 1)
                        su += __shfl_xor_sync(0xffffffffu, su, kk, 16);
                    if (ii < NC && jr < 64) cb[j * 12 + ii] = e * (1.0f / su);
                }
                if (k < NTILE - 1) bar_arrive(5, 640);   // bp free for B(k+1)
                bar_sync(4, 320);                        // cb visible across wg1

                // ---- C: yacc[i] += c[i,j] * x[j, d0c..d0c+1] (32 j) ----
                if (t2 < 300) {
                    #pragma unroll
                    for (int jj = 0; jj < 32; ++jj) {
                        const int j = j0 + jj;
                        const u64 xv = *(const u64*)(xs + j * DD + d0c);
                        const float4 c0 = *(const float4*)(cb + j * 12);
                        const float4 c1 = *(const float4*)(cb + j * 12 + 4);
                        const float2 c2v = *(const float2*)(cb + j * 12 + 8);
                        fma2(yacc[0], xv, splat2(c0.x));
                        fma2(yacc[1], xv, splat2(c0.y));
                        fma2(yacc[2], xv, splat2(c0.z));
                        fma2(yacc[3], xv, splat2(c0.w));
                        fma2(yacc[4], xv, splat2(c1.x));
                        fma2(yacc[5], xv, splat2(c1.y));
                        fma2(yacc[6], xv, splat2(c1.z));
                        fma2(yacc[7], xv, splat2(c1.w));
                        fma2(yacc[8], xv, splat2(c2v.x));
                        fma2(yacc[9], xv, splat2(c2v.y));
                    }
                }
                bar_arrive(2, 640);                  // C(k) done
            }
            if (t2 < 300) {
                #pragma unroll
                for (int i = 0; i < NC; ++i)
                    *(u64*)(yp + jg * 3000 + i * DD + d0c) = yacc[i];
            }
        }
        __syncthreads();
        for (int idx = t; idx < NC * DD; idx += NT)
            y_s[idx] = yp[idx] + yp[3000 + idx];
        __syncthreads();
    }
}

extern "C" void kernel_launch(void* const* d_in, const int* in_sizes, int n_in,
                              void* d_out, int out_size)
{
    const float* x = (const float*)d_in[0];
    const float* W = (const float*)d_in[1];
    if (n_in >= 2 && in_sizes[0] < in_sizes[1]) {
        x = (const float*)d_in[1];
        W = (const float*)d_in[0];
    }
    float* out = (float*)d_out;

    static int attr_done = 0;
    if (!attr_done) {
        cudaFuncSetAttribute(caps_kernel, cudaFuncAttributeMaxDynamicSharedMemorySize,
                             SMEM_BYTES);
        attr_done = 1;
    }

    dim3 tb(32, 8);
    dim3 tg(MM / 32, (DD + 31) / 32);
    transpose_W<<<tg, tb>>>(W);
    caps_kernel<<<BB, NT, SMEM_BYTES>>>(x, W, out);
}

// round 13
// speedup vs baseline: 1.0254x; 1.0254x over previous
#include <cuda_runtime.h>

// Caps_Layer: B=128, N=512, D=300, NC=10, DC=64, ROUTINGS=5  (fused, 1 CTA/batch)
// u never materialized. x read straight from L2 (no smem staging, no cp.async).
// Per iteration:
//   P2: o_raw[m] = sum_d y[i,d] W[d,m] (float4 y bcasts) ; squash -> o
//   P3: v[i,d] = sum_k o[i,k] Wt[i*64+k,d] (float4 o bcasts; W pre-transposed)
//   XPASS (warp-specialized, 8 j-tiles of 64):
//     wg0 (w0-9):  B(k): b = x(LDG) * v(smem bcast), 2 j-cols per lane -> bp[k&1]
//     wg1 (w10-19): softmax(k) bp[k&1] -> cb ; C(k): y += c * x(LDG), reg yacc
//     bars: id1 B(k)->wg1 ; id4 wg1-local cb visibility ;
//           id5 "wg1 entered tile k" -> wg0 may start B(k+1).
//     Generation safety: wg0's consecutive bar1 arrives are separated by a bar5
//     sync whose release requires a wg1 arrive that follows wg1's bar1 sync.

#define NN 512
#define DD 300
#define NC 10
#define DC 64
#define MM 640
#define BB 128
#define NT 640
#define TJ 64
#define NTILE 8

#define OFF_V   0        // 3000
#define OFF_Y   3000     // 3000
#define OFF_YP  6000     // 6000 (2 j-group partials)
#define OFF_BP  12000    // 2 x 7040 (parity; also P2 scratch 2560, it0 600)
#define OFF_C   26080    // 768  (c[j*12 + i], 64 j)
#define OFF_O   26848    // 640
#define OFF_NRM 27488    // 16
#define SMEM_FLOATS 27504
#define SMEM_BYTES (SMEM_FLOATS * 4)   // 110016 B

typedef unsigned long long u64;
struct u64x2_t { u64 x, y; };

__device__ float Wt_g[MM * DD];   // W transposed: Wt[m*300 + d]

__device__ __forceinline__ void fma2(u64& acc, u64 a, u64 b) {
    asm("fma.rn.f32x2 %0, %1, %2, %0;" : "+l"(acc) : "l"(a), "l"(b));
}
__device__ __forceinline__ u64 splat2(float f) {
    u64 r; asm("mov.b64 %0, {%1,%1};" : "=l"(r) : "f"(f)); return r;
}
__device__ __forceinline__ float fold2(u64 v) {
    float lo, hi; asm("mov.b64 {%0,%1}, %2;" : "=f"(lo), "=f"(hi) : "l"(v)); return lo + hi;
}
__device__ __forceinline__ void bar_arrive(int id, int cnt) {
    asm volatile("bar.arrive %0, %1;" :: "r"(id), "r"(cnt) : "memory");
}
__device__ __forceinline__ void bar_sync(int id, int cnt) {
    asm volatile("bar.sync %0, %1;" :: "r"(id), "r"(cnt) : "memory");
}

// ---------------- prologue: W[300][640] -> Wt[640][300] ----------------
__global__ void transpose_W(const float* __restrict__ W)
{
    __shared__ float tl[32][33];
    const int tx = threadIdx.x, ty = threadIdx.y;     // 32 x 8
    const int m0 = blockIdx.x * 32, d0 = blockIdx.y * 32;
    #pragma unroll
    for (int k = 0; k < 4; ++k) {
        const int d = d0 + ty + k * 8;
        if (d < DD) tl[ty + k * 8][tx] = W[(size_t)d * MM + m0 + tx];
    }
    __syncthreads();
    #pragma unroll
    for (int k = 0; k < 4; ++k) {
        const int m = m0 + ty + k * 8;
        const int d = d0 + tx;
        if (d < DD) Wt_g[(size_t)m * DD + d] = tl[tx][ty + k * 8];
    }
}

__global__ __launch_bounds__(NT, 1)
void caps_kernel(const float* __restrict__ x,
                 const float* __restrict__ W,
                 float* __restrict__ out)
{
    extern __shared__ float sm[];
    const int b    = blockIdx.x;
    const int t    = threadIdx.x;
    const int w    = t >> 5;
    const int lane = t & 31;
    const float* __restrict__ xb = x + (size_t)b * NN * DD;

    float* v_s  = sm + OFF_V;
    float* y_s  = sm + OFF_Y;
    float* yp   = sm + OFF_YP;
    float* bp   = sm + OFF_BP;
    float* cb   = sm + OFF_C;
    float* o_s  = sm + OFF_O;
    float* nrm  = sm + OFF_NRM;

    // ---- iteration 0: y[i,d] = 0.1 * colsum_d(x) ----
    if (t < 600) {
        const int g = t / 300, d = t - g * 300;
        const float* __restrict__ xp = xb + (size_t)(g * 256) * DD + d;
        float a0 = 0.f, a1 = 0.f, a2 = 0.f, a3 = 0.f;
        for (int j = 0; j < 256; j += 4) {
            a0 += xp[(j + 0) * DD]; a1 += xp[(j + 1) * DD];
            a2 += xp[(j + 2) * DD]; a3 += xp[(j + 3) * DD];
        }
        bp[g * 300 + d] = (a0 + a1) + (a2 + a3);
    }
    __syncthreads();
    for (int idx = t; idx < NC * DD; idx += NT) {
        const int d = idx % DD;
        y_s[idx] = 0.1f * (bp[d] + bp[300 + d]);
    }
    __syncthreads();

    for (int r = 0; r < 5; ++r) {
        // ---------------- P2: o_raw[m] = sum_d y[i,d] W[d,m] ----------------
        {
            const int ds  = t / 160;            // d-slice 0..3 (76/76/76/72)
            const int m4  = (t - ds * 160) * 4;
            const int ci  = m4 >> 6;
            const int d0  = ds * 76;
            const int len = (ds < 3) ? 76 : 72;
            const float* __restrict__ ypt = y_s + ci * DD;
            u64 a01 = 0ull, a23 = 0ull;
            for (int d = d0; d < d0 + len; d += 4) {
                const float4 y4 = *(const float4*)(ypt + d);
                #pragma unroll
                for (int q = 0; q < 4; ++q) {
                    const u64x2_t w4 = *(const u64x2_t*)(W + (size_t)(d + q) * MM + m4);
                    const float yq = (q == 0) ? y4.x : (q == 1) ? y4.y : (q == 2) ? y4.z : y4.w;
                    const u64 ys = splat2(yq);
                    fma2(a01, w4.x, ys); fma2(a23, w4.y, ys);
                }
            }
            *(u64*)(bp + ds * MM + m4)     = a01;
            *(u64*)(bp + ds * MM + m4 + 2) = a23;
        }
        __syncthreads();
        o_s[t] = bp[t] + bp[MM + t] + bp[2 * MM + t] + bp[3 * MM + t];
        __syncthreads();
        if (t < 320) {   // squash norms
            const int i = t >> 5;
            const float v0 = o_s[i * DC + lane];
            const float v1 = o_s[i * DC + 32 + lane];
            float s = v0 * v0 + v1 * v1;
            #pragma unroll
            for (int k = 16; k > 0; k >>= 1) s += __shfl_xor_sync(0xffffffffu, s, k);
            if (lane == 0) nrm[i] = rsqrtf(s + 1e-7f);
        }
        __syncthreads();
        const float ov = o_s[t] * nrm[t >> 6];
        o_s[t] = ov;
        if (r == 4) { out[(size_t)b * MM + t] = ov; break; }
        __syncthreads();

        // ---------------- P3: v[i,d] = sum_k o[i,k] Wt[i*64+k, d] ----------------
        for (int idx = t; idx < NC * 150; idx += NT) {
            const int i  = idx / 150;
            const int d0 = (idx - i * 150) * 2;
            const float* __restrict__ ob = o_s + i * DC;
            const float* __restrict__ wt = Wt_g + (size_t)i * DC * DD + d0;
            u64 acc = 0ull;
            #pragma unroll 4
            for (int k4 = 0; k4 < 16; ++k4) {
                const float4 o4 = *(const float4*)(ob + k4 * 4);
                fma2(acc, *(const u64*)(wt + (size_t)(k4 * 4 + 0) * DD), splat2(o4.x));
                fma2(acc, *(const u64*)(wt + (size_t)(k4 * 4 + 1) * DD), splat2(o4.y));
                fma2(acc, *(const u64*)(wt + (size_t)(k4 * 4 + 2) * DD), splat2(o4.z));
                fma2(acc, *(const u64*)(wt + (size_t)(k4 * 4 + 3) * DD), splat2(o4.w));
            }
            *(u64*)(v_s + i * DD + d0) = acc;
        }
        __syncthreads();

        // ---------------- XPASS: warp-specialized, x via LDG ----------------
        if (t < 320) {
            // ===== wg0: B only =====
            const int dB  = (w < 9) ? w * 32 : 288;
            const int n16 = (w < 9) ? 8 : 3;

            for (int k = 0; k < NTILE; ++k) {
                if (k >= 1) bar_sync(5, 640);        // wg1 entered tile k-1: safe to
                                                     // write bp[k&1] and re-arrive bar1
                const float* __restrict__ xA  = xb + (size_t)(k * TJ + lane) * DD + dB;
                const float* __restrict__ xB2 = xA + 32 * DD;
                u64 accA[NC], accB[NC];
                #pragma unroll
                for (int i = 0; i < NC; ++i) { accA[i] = 0ull; accB[i] = 0ull; }
                for (int s = 0; s < n16; ++s) {
                    const u64x2_t xvA = *(const u64x2_t*)(xA + s * 4);
                    const u64x2_t xvB = *(const u64x2_t*)(xB2 + s * 4);
                    #pragma unroll
                    for (int i = 0; i < NC; ++i) {
                        const u64x2_t vv = *(const u64x2_t*)(v_s + i * DD + dB + s * 4);
                        fma2(accA[i], xvA.x, vv.x);
                        fma2(accA[i], xvA.y, vv.y);
                        fma2(accB[i], xvB.x, vv.x);
                        fma2(accB[i], xvB.y, vv.y);
                    }
                }
                float* bpk = bp + (k & 1) * 7040;
                #pragma unroll
                for (int i = 0; i < NC; ++i) {
                    bpk[w * 704 + lane * 11 + i]        = fold2(accA[i]);
                    bpk[w * 704 + (lane + 32) * 11 + i] = fold2(accB[i]);
                }
                bar_arrive(1, 640);                  // B(k) ready
            }
        } else {
            // ===== wg1: softmax + C =====
            const int t2  = t - 320;                 // 0..319
            const int jg  = t2 / 150;                // valid for t2<300
            const int d0c = (t2 - jg * 150) * 2;
            const int j0  = jg * 32;
            u64 yacc[NC];
            #pragma unroll
            for (int i = 0; i < NC; ++i) yacc[i] = 0ull;

            for (int k = 0; k < NTILE; ++k) {
                bar_sync(1, 640);                    // wait B(k)
                if (k < NTILE - 1) bar_arrive(5, 640);   // signal "entered tile k"
                const float* bpk = bp + (k & 1) * 7040;

                // ---- softmax over i per j: 4 clamped rounds of 20 groups ----
                #pragma unroll
                for (int rd = 0; rd < 4; ++rd) {
                    const int jr = rd * 20 + (t2 >> 4);
                    const int j  = (jr < 64) ? jr : 63;
                    const int ii = t2 & 15;
                    float s;
                    if (ii < NC) {
                        s = 0.f;
                        #pragma unroll
                        for (int ww = 0; ww < 10; ++ww)
                            s += bpk[ww * 704 + j * 11 + ii];
                    } else s = -1e30f;
                    float m = s;
                    #pragma unroll
                    for (int kk = 8; kk > 0; kk >>= 1)
                        m = fmaxf(m, __shfl_xor_sync(0xffffffffu, m, kk, 16));
                    const float e = __expf(s - m);
                    float su = e;
                    #pragma unroll
                    for (int kk = 8; kk > 0; kk >>= 1)
                        su += __shfl_xor_sync(0xffffffffu, su, kk, 16);
                    if (ii < NC && jr < 64) cb[j * 12 + ii] = e * (1.0f / su);
                }
                bar_sync(4, 320);                    // cb visible across wg1

                // ---- C: yacc[i] += c[i,j] * x[j, d0c..d0c+1] (32 j, x via LDG) ----
                if (t2 < 300) {
                    const float* __restrict__ xg = xb + (size_t)(k * TJ) * DD + d0c;
                    #pragma unroll 8
                    for (int jj = 0; jj < 32; ++jj) {
                        const int j = j0 + jj;
                        const u64 xv = *(const u64*)(xg + (size_t)j * DD);
                        const float4 c0 = *(const float4*)(cb + j * 12);
                        const float4 c1 = *(const float4*)(cb + j * 12 + 4);
                        const float2 c2v = *(const float2*)(cb + j * 12 + 8);
                        fma2(yacc[0], xv, splat2(c0.x));
                        fma2(yacc[1], xv, splat2(c0.y));
                        fma2(yacc[2], xv, splat2(c0.z));
                        fma2(yacc[3], xv, splat2(c0.w));
                        fma2(yacc[4], xv, splat2(c1.x));
                        fma2(yacc[5], xv, splat2(c1.y));
                        fma2(yacc[6], xv, splat2(c1.z));
                        fma2(yacc[7], xv, splat2(c1.w));
                        fma2(yacc[8], xv, splat2(c2v.x));
                        fma2(yacc[9], xv, splat2(c2v.y));
                    }
                }
            }
            if (t2 < 300) {
                #pragma unroll
                for (int i = 0; i < NC; ++i)
                    *(u64*)(yp + jg * 3000 + i * DD + d0c) = yacc[i];
            }
        }
        __syncthreads();
        for (int idx = t; idx < NC * DD; idx += NT)
            y_s[idx] = yp[idx] + yp[3000 + idx];
        __syncthreads();
    }
}

extern "C" void kernel_launch(void* const* d_in, const int* in_sizes, int n_in,
                              void* d_out, int out_size)
{
    const float* x = (const float*)d_in[0];
    const float* W = (const float*)d_in[1];
    if (n_in >= 2 && in_sizes[0] < in_sizes[1]) {
        x = (const float*)d_in[1];
        W = (const float*)d_in[0];
    }
    float* out = (float*)d_out;

    static int attr_done = 0;
    if (!attr_done) {
        cudaFuncSetAttribute(caps_kernel, cudaFuncAttributeMaxDynamicSharedMemorySize,
                             SMEM_BYTES);
        attr_done = 1;
    }

    dim3 tb(32, 8);
    dim3 tg(MM / 32, (DD + 31) / 32);
    transpose_W<<<tg, tb>>>(W);
    caps_kernel<<<BB, NT, SMEM_BYTES>>>(x, W, out);
}

// round 15
// speedup vs baseline: 1.1869x; 1.1575x over previous
#include <cuda_runtime.h>

// Caps_Layer: B=128, N=512, D=300, NC=10, DC=64, ROUTINGS=5  (fused, 1 CTA/batch)
// u never materialized. Per iteration:
//   P2: o_raw[m] = sum_d y[i,d] W[d,m] (float4 y bcasts) ; squash -> o
//   P3: v[i,d] = sum_k o[i,k] Wt[i*64+k,d] (float4 o bcasts; W pre-transposed)
//   XPASS (warp-specialized, 8 j-tiles of 64):
//     wg0 (w0-9):  cp.async ring (2 bufs, consumed ONLY by wg0) ;
//                  B(k): b = x(LDS) * v(bcast), 2 j-cols per lane -> bp[k&1]
//     wg1 (w10-19): softmax(k) bp[k&1] -> cb(=o_s overlay) ; C(k): y += c * x(LDG)
//     bars: id1 B(k)->wg1 ; id3 wg0-local (x2: ring-reuse guard + cp visibility) ;
//           id4 wg1-local cb ; id5 "wg1 entered tile k" -> wg0 may start B(k+1).
//     R14 race FIXED: bar3 at top of tile k ensures ALL wg0 warps finished B(k-1)
//     before any warp's cp.async overwrites buf[(k+1)&1].

#define NN 512
#define DD 300
#define NC 10
#define DC 64
#define MM 640
#define BB 128
#define NT 640
#define TJ 64
#define NTILE 8
#define AR_BUF (TJ * DD)          // 19200 floats per buffer

#define OFF_AR  0                 // 2 bufs = 38400 (yp[6000] overlays buf0 at flush)
#define OFF_V   38400             // 3000
#define OFF_Y   41400             // 3000
#define OFF_BP  44400             // 2 x 6400 (parity, stride-10; P2 scratch, it0)
#define OFF_CBO 57200             // 768: cb[j*12+i] (XPASS) / o_s[640] (P2,P3) overlay
#define OFF_NRM 57968             // 16
#define SMEM_FLOATS 57984
#define SMEM_BYTES (SMEM_FLOATS * 4)   // 231936 B

typedef unsigned long long u64;
struct u64x2_t { u64 x, y; };

__device__ float Wt_g[MM * DD];   // W transposed: Wt[m*300 + d]

__device__ __forceinline__ void fma2(u64& acc, u64 a, u64 b) {
    asm("fma.rn.f32x2 %0, %1, %2, %0;" : "+l"(acc) : "l"(a), "l"(b));
}
__device__ __forceinline__ u64 splat2(float f) {
    u64 r; asm("mov.b64 %0, {%1,%1};" : "=l"(r) : "f"(f)); return r;
}
__device__ __forceinline__ float fold2(u64 v) {
    float lo, hi; asm("mov.b64 {%0,%1}, %2;" : "=f"(lo), "=f"(hi) : "l"(v)); return lo + hi;
}
__device__ __forceinline__ void cp16(void* smem_dst, const void* gsrc) {
    unsigned sa = (unsigned)__cvta_generic_to_shared(smem_dst);
    asm volatile("cp.async.cg.shared.global [%0], [%1], 16;" :: "r"(sa), "l"(gsrc));
}
__device__ __forceinline__ void cp_commit() { asm volatile("cp.async.commit_group;"); }
template <int N> __device__ __forceinline__ void cp_wait() {
    asm volatile("cp.async.wait_group %0;" :: "n"(N));
}
__device__ __forceinline__ void bar_arrive(int id, int cnt) {
    asm volatile("bar.arrive %0, %1;" :: "r"(id), "r"(cnt) : "memory");
}
__device__ __forceinline__ void bar_sync(int id, int cnt) {
    asm volatile("bar.sync %0, %1;" :: "r"(id), "r"(cnt) : "memory");
}

// ---------------- prologue: W[300][640] -> Wt[640][300] ----------------
__global__ void transpose_W(const float* __restrict__ W)
{
    __shared__ float tl[32][33];
    const int tx = threadIdx.x, ty = threadIdx.y;     // 32 x 8
    const int m0 = blockIdx.x * 32, d0 = blockIdx.y * 32;
    #pragma unroll
    for (int k = 0; k < 4; ++k) {
        const int d = d0 + ty + k * 8;
        if (d < DD) tl[ty + k * 8][tx] = W[(size_t)d * MM + m0 + tx];
    }
    __syncthreads();
    #pragma unroll
    for (int k = 0; k < 4; ++k) {
        const int m = m0 + ty + k * 8;
        const int d = d0 + tx;
        if (d < DD) Wt_g[(size_t)m * DD + d] = tl[tx][ty + k * 8];
    }
}

__global__ __launch_bounds__(NT, 1)
void caps_kernel(const float* __restrict__ x,
                 const float* __restrict__ W,
                 float* __restrict__ out)
{
    extern __shared__ float sm[];
    const int b    = blockIdx.x;
    const int t    = threadIdx.x;
    const int w    = t >> 5;
    const int lane = t & 31;
    const float* __restrict__ xb = x + (size_t)b * NN * DD;

    float* v_s  = sm + OFF_V;
    float* y_s  = sm + OFF_Y;
    float* bp   = sm + OFF_BP;
    float* cb   = sm + OFF_CBO;       // XPASS lifetime
    float* o_s  = sm + OFF_CBO;       // P2/P3 lifetime (overlay)
    float* nrm  = sm + OFF_NRM;
    float* yp   = sm + OFF_AR;        // overlay on x buf0, valid only at flush

    // ---- iteration 0: y[i,d] = 0.1 * colsum_d(x) ----
    if (t < 600) {
        const int g = t / 300, d = t - g * 300;
        const float* __restrict__ xp = xb + (size_t)(g * 256) * DD + d;
        float a0 = 0.f, a1 = 0.f, a2 = 0.f, a3 = 0.f;
        for (int j = 0; j < 256; j += 4) {
            a0 += xp[(j + 0) * DD]; a1 += xp[(j + 1) * DD];
            a2 += xp[(j + 2) * DD]; a3 += xp[(j + 3) * DD];
        }
        bp[g * 300 + d] = (a0 + a1) + (a2 + a3);
    }
    __syncthreads();
    for (int idx = t; idx < NC * DD; idx += NT) {
        const int d = idx % DD;
        y_s[idx] = 0.1f * (bp[d] + bp[300 + d]);
    }
    __syncthreads();

    for (int r = 0; r < 5; ++r) {
        // ---------------- P2: o_raw[m] = sum_d y[i,d] W[d,m] ----------------
        {
            const int ds  = t / 160;            // d-slice 0..3 (76/76/76/72)
            const int m4  = (t - ds * 160) * 4;
            const int ci  = m4 >> 6;
            const int d0  = ds * 76;
            const int len = (ds < 3) ? 76 : 72;
            const float* __restrict__ ypt = y_s + ci * DD;
            u64 a01 = 0ull, a23 = 0ull;
            for (int d = d0; d < d0 + len; d += 4) {
                const float4 y4 = *(const float4*)(ypt + d);
                #pragma unroll
                for (int q = 0; q < 4; ++q) {
                    const u64x2_t w4 = *(const u64x2_t*)(W + (size_t)(d + q) * MM + m4);
                    const float yq = (q == 0) ? y4.x : (q == 1) ? y4.y : (q == 2) ? y4.z : y4.w;
                    const u64 ys = splat2(yq);
                    fma2(a01, w4.x, ys); fma2(a23, w4.y, ys);
                }
            }
            *(u64*)(bp + ds * MM + m4)     = a01;
            *(u64*)(bp + ds * MM + m4 + 2) = a23;
        }
        __syncthreads();
        o_s[t] = bp[t] + bp[MM + t] + bp[2 * MM + t] + bp[3 * MM + t];
        __syncthreads();
        if (t < 320) {   // squash norms
            const int i = t >> 5;
            const float v0 = o_s[i * DC + lane];
            const float v1 = o_s[i * DC + 32 + lane];
            float s = v0 * v0 + v1 * v1;
            #pragma unroll
            for (int k = 16; k > 0; k >>= 1) s += __shfl_xor_sync(0xffffffffu, s, k);
            if (lane == 0) nrm[i] = rsqrtf(s + 1e-7f);
        }
        __syncthreads();
        const float ov = o_s[t] * nrm[t >> 6];
        o_s[t] = ov;
        if (r == 4) { out[(size_t)b * MM + t] = ov; break; }
        __syncthreads();

        // ---------------- P3: v[i,d] = sum_k o[i,k] Wt[i*64+k, d] ----------------
        for (int idx = t; idx < NC * 150; idx += NT) {
            const int i  = idx / 150;
            const int d0 = (idx - i * 150) * 2;
            const float* __restrict__ ob = o_s + i * DC;
            const float* __restrict__ wt = Wt_g + (size_t)i * DC * DD + d0;
            u64 acc = 0ull;
            #pragma unroll 4
            for (int k4 = 0; k4 < 16; ++k4) {
                const float4 o4 = *(const float4*)(ob + k4 * 4);
                fma2(acc, *(const u64*)(wt + (size_t)(k4 * 4 + 0) * DD), splat2(o4.x));
                fma2(acc, *(const u64*)(wt + (size_t)(k4 * 4 + 1) * DD), splat2(o4.y));
                fma2(acc, *(const u64*)(wt + (size_t)(k4 * 4 + 2) * DD), splat2(o4.z));
                fma2(acc, *(const u64*)(wt + (size_t)(k4 * 4 + 3) * DD), splat2(o4.w));
            }
            *(u64*)(v_s + i * DD + d0) = acc;
        }
        __syncthreads();   // o_s dead from here; cb may be written in XPASS

        // ---------------- XPASS ----------------
        if (t < 320) {
            // ===== wg0: cp.async ring + B =====
            for (int idx = t; idx < AR_BUF / 4; idx += 320)     // prologue: tile 0
                cp16(sm + OFF_AR + idx * 4, xb + idx * 4);
            cp_commit();

            const int dB  = (w < 9) ? w * 32 : 288;
            const int n16 = (w < 9) ? 8 : 3;

            for (int k = 0; k < NTILE; ++k) {
                // RACE FIX: all wg0 warps must be done with B(k-1) (which read
                // buf[(k+1)&1]) before ANY warp overwrites that buffer.
                if (k >= 1) bar_sync(3, 320);
                if (k + 1 < NTILE) {
                    const float* gs = xb + (size_t)(k + 1) * AR_BUF;
                    float* dst = sm + OFF_AR + ((k + 1) & 1) * AR_BUF;
                    for (int idx = t; idx < AR_BUF / 4; idx += 320)
                        cp16(dst + idx * 4, gs + idx * 4);
                    cp_commit();
                    cp_wait<1>();                 // tile k landed
                } else {
                    cp_wait<0>();
                }
                bar_sync(3, 320);                 // tile k visible across wg0
                if (k >= 1) bar_sync(5, 640);     // wg1 entered tile k-1
                const float* xs = sm + OFF_AR + (k & 1) * AR_BUF;

                // ---- B: b[i, j=lane] and b[i, j=lane+32], shared v broadcasts ----
                u64 accA[NC], accB[NC];
                #pragma unroll
                for (int i = 0; i < NC; ++i) { accA[i] = 0ull; accB[i] = 0ull; }
                const float* xrowA = xs + lane * DD + dB;
                const float* xrowB = xrowA + 32 * DD;
                for (int s = 0; s < n16; ++s) {
                    const u64x2_t xvA = *(const u64x2_t*)(xrowA + s * 4);
                    const u64x2_t xvB = *(const u64x2_t*)(xrowB + s * 4);
                    #pragma unroll
                    for (int i = 0; i < NC; ++i) {
                        const u64x2_t vv = *(const u64x2_t*)(v_s + i * DD + dB + s * 4);
                        fma2(accA[i], xvA.x, vv.x);
                        fma2(accA[i], xvA.y, vv.y);
                        fma2(accB[i], xvB.x, vv.x);
                        fma2(accB[i], xvB.y, vv.y);
                    }
                }
                float* bpk = bp + (k & 1) * 6400;
                #pragma unroll
                for (int i = 0; i < NC; ++i) {
                    bpk[w * 640 + lane * 10 + i]        = fold2(accA[i]);
                    bpk[w * 640 + (lane + 32) * 10 + i] = fold2(accB[i]);
                }
                bar_arrive(1, 640);               // B(k) ready
            }
        } else {
            // ===== wg1: softmax + C (x via LDG: coalesced per j-row) =====
            const int t2  = t - 320;              // 0..319
            const int jg  = t2 / 150;             // valid for t2<300
            const int d0c = (t2 - jg * 150) * 2;
            const int j0  = jg * 32;
            u64 yacc[NC];
            #pragma unroll
            for (int i = 0; i < NC; ++i) yacc[i] = 0ull;

            for (int k = 0; k < NTILE; ++k) {
                bar_sync(1, 640);                 // wait B(k)
                if (k < NTILE - 1) bar_arrive(5, 640);  // "entered tile k"
                const float* bpk = bp + (k & 1) * 6400;

                // ---- softmax over i per j: 4 clamped rounds of 20 groups ----
                #pragma unroll
                for (int rd = 0; rd < 4; ++rd) {
                    const int jr = rd * 20 + (t2 >> 4);
                    const int j  = (jr < 64) ? jr : 63;
                    const int ii = t2 & 15;
                    float s;
                    if (ii < NC) {
                        s = 0.f;
                        #pragma unroll
                        for (int ww = 0; ww < 10; ++ww)
                            s += bpk[ww * 640 + j * 10 + ii];
                    } else s = -1e30f;
                    float m = s;
                    #pragma unroll
                    for (int kk = 8; kk > 0; kk >>= 1)
                        m = fmaxf(m, __shfl_xor_sync(0xffffffffu, m, kk, 16));
                    const float e = __expf(s - m);
                    float su = e;
                    #pragma unroll
                    for (int kk = 8; kk > 0; kk >>= 1)
                        su += __shfl_xor_sync(0xffffffffu, su, kk, 16);
                    if (ii < NC && jr < 64) cb[j * 12 + ii] = e * (1.0f / su);
                }
                bar_sync(4, 320);                 // cb visible across wg1

                // ---- C: yacc[i] += c[i,j] * x[j, d0c..d0c+1] (32 j, LDG) ----
                if (t2 < 300) {
                    const float* __restrict__ xg = xb + (size_t)(k * TJ) * DD + d0c;
                    #pragma unroll 8
                    for (int jj = 0; jj < 32; ++jj) {
                        const int j = j0 + jj;
                        const u64 xv = *(const u64*)(xg + (size_t)j * DD);
                        const float4 c0 = *(const float4*)(cb + j * 12);
                        const float4 c1 = *(const float4*)(cb + j * 12 + 4);
                        const float2 c2v = *(const float2*)(cb + j * 12 + 8);
                        fma2(yacc[0], xv, splat2(c0.x));
                        fma2(yacc[1], xv, splat2(c0.y));
                        fma2(yacc[2], xv, splat2(c0.z));
                        fma2(yacc[3], xv, splat2(c0.w));
                        fma2(yacc[4], xv, splat2(c1.x));
                        fma2(yacc[5], xv, splat2(c1.y));
                        fma2(yacc[6], xv, splat2(c1.z));
                        fma2(yacc[7], xv, splat2(c1.w));
                        fma2(yacc[8], xv, splat2(c2v.x));
                        fma2(yacc[9], xv, splat2(c2v.y));
                    }
                }
            }
            // flush: wg0's last buf0 write was tile-6 prefetch, consumed by B(6);
            // all B done before wg1 leaves k=7 (bar1), so yp overlay is safe.
            if (t2 < 300) {
                #pragma unroll
                for (int i = 0; i < NC; ++i)
                    *(u64*)(yp + jg * 3000 + i * DD + d0c) = yacc[i];
            }
        }
        __syncthreads();
        for (int idx = t; idx < NC * DD; idx += NT)
            y_s[idx] = yp[idx] + yp[3000 + idx];
        __syncthreads();
    }
}

extern "C" void kernel_launch(void* const* d_in, const int* in_sizes, int n_in,
                              void* d_out, int out_size)
{
    const float* x = (const float*)d_in[0];
    const float* W = (const float*)d_in[1];
    if (n_in >= 2 && in_sizes[0] < in_sizes[1]) {
        x = (const float*)d_in[1];
        W = (const float*)d_in[0];
    }
    float* out = (float*)d_out;

    static int attr_done = 0;
    if (!attr_done) {
        cudaFuncSetAttribute(caps_kernel, cudaFuncAttributeMaxDynamicSharedMemorySize,
                             SMEM_BYTES);
        attr_done = 1;
    }

    dim3 tb(32, 8);
    dim3 tg(MM / 32, (DD + 31) / 32);
    transpose_W<<<tg, tb>>>(W);
    caps_kernel<<<BB, NT, SMEM_BYTES>>>(x, W, out);
}